// round 5
// baseline (speedup 1.0000x reference)
#include <cuda_runtime.h>

// ---------------------------------------------------------------------------
// ST_Block: 66-step spatio-temporal orthogonal basis recursion + fused MLP/BN.
//
// Per step r the producing GEMM kernel also emits 6 full-slab dot products
// (deterministic tree reduction into g_part ping-pong). The *next* kernel
// derives the Gram-Schmidt coefficients + analytic residual norm from those
// scalars and performs the normalization + theta-accumulation as a
// region-local prologue (fused update). Only the very last step needs a
// standalone update. 69 graph nodes total, no atomics.
// ---------------------------------------------------------------------------

#define BB   4
#define CC   16
#define CH   64              // B*C chains
#define NN   512
#define TT   64
#define SLAB (NN*TT)         // 32768 floats per chain slab
#define CSZ  (CH*SLAB)       // floats per full slab
#define NSLAB 7
#define ACCS  6              // slab index reserved for x_st accumulator
#define RTOT  66

__device__ __align__(16) float g_slab[NSLAB * CSZ];   // ~58.7 MB scratch
__device__ float g_part[2][CH][4][6];                 // ping-pong dot partials
__device__ float g_theta[BB][RTOT];

__device__ __forceinline__ float warp_sum(float v) {
    v += __shfl_down_sync(0xffffffffu, v, 16);
    v += __shfl_down_sync(0xffffffffu, v, 8);
    v += __shfl_down_sync(0xffffffffu, v, 4);
    v += __shfl_down_sync(0xffffffffu, v, 2);
    v += __shfl_down_sync(0xffffffffu, v, 1);
    return v;
}

// Derive d1, d2, 1/norm, theta from the 6 summed dots.
//   d1 = <V,L>;  d2 = <V,S> - d1*<L,S>
//   ||rst2||^2 = p3 - 2 d1 p1 - 2 d2 p2 + d1^2 p5 + d2^2 p6 + 2 d1 d2 p4
__device__ __forceinline__ void derive_scalars(int readPP, int chain, int rUpd,
                                               float* sc) {
    float p[6];
    #pragma unroll
    for (int c = 0; c < 6; c++) {
        float t = 0.f;
        #pragma unroll
        for (int tl = 0; tl < 4; tl++) t += g_part[readPP][chain][tl][c];
        p[c] = t;
    }
    float d1 = p[0];
    float d2 = p[1] - d1 * p[3];
    float n2 = p[2] - 2.f * d1 * p[0] - 2.f * d2 * p[1]
             + d1 * d1 * p[4] + d2 * d2 * p[5] + 2.f * d1 * d2 * p[3];
    sc[0] = d1;
    sc[1] = d2;
    sc[2] = 1.f / fmaxf(sqrtf(fmaxf(n2, 0.f)), 1e-8f);
    sc[3] = g_theta[chain >> 4][rUpd];
}

// ---------------------------------------------------------------------------
// theta: tiny MLP on STE. theta[b][q*11+p] = relu(h2[b,p,q])
// ---------------------------------------------------------------------------
__global__ void k_theta(const float* __restrict__ STE, const float* __restrict__ w1,
                        const float* __restrict__ b1, const float* __restrict__ w2,
                        const float* __restrict__ b2) {
    int idx = threadIdx.x;
    if (idx >= BB * RTOT) return;
    int b = idx / RTOT, rr = idx % RTOT;
    int q = rr / 11, p = rr % 11;
    float acc = b2[p];
    #pragma unroll
    for (int s = 0; s < 10; s++) {
        float h1 = b1[q];
        #pragma unroll
        for (int t = 0; t < 5; t++)
            h1 += w1[q * 5 + t] * STE[b * 50 + t * 10 + s];
        acc += w2[p * 10 + s] * h1;
    }
    g_theta[b][rr] = fmaxf(acc, 0.f);
}

// ---------------------------------------------------------------------------
// init: m00 = x / max(||x||_F, eps) into slab 0; acc = theta_0 * m00
// ---------------------------------------------------------------------------
__global__ void __launch_bounds__(256) k_init(const float* __restrict__ x) {
    int chain = blockIdx.x;
    const float* xp = x + chain * SLAB;
    float* m = g_slab + 0 * CSZ + chain * SLAB;
    float* a = g_slab + ACCS * CSZ + chain * SLAB;
    int tid = threadIdx.x;

    float s = 0.f;
    #pragma unroll
    for (int i = 0; i < 32; i++) {
        float4 v = *(const float4*)(xp + (i * 256 + tid) * 4);
        s += v.x * v.x + v.y * v.y + v.z * v.z + v.w * v.w;
    }
    __shared__ float red[8];
    __shared__ float sinv;
    float w = warp_sum(s);
    if ((tid & 31) == 0) red[tid >> 5] = w;
    __syncthreads();
    if (tid == 0) {
        float t = 0.f;
        #pragma unroll
        for (int k = 0; k < 8; k++) t += red[k];
        sinv = 1.f / fmaxf(sqrtf(t), 1e-8f);
    }
    __syncthreads();
    float inv = sinv;
    float th = g_theta[chain >> 4][0];
    #pragma unroll
    for (int i = 0; i < 32; i++) {
        int o = (i * 256 + tid) * 4;
        float4 v = *(const float4*)(xp + o);
        float4 mm, aa;
        mm.x = v.x * inv; mm.y = v.y * inv; mm.z = v.z * inv; mm.w = v.w * inv;
        aa.x = th * mm.x; aa.y = th * mm.y; aa.z = th * mm.z; aa.w = th * mm.w;
        *(float4*)(m + o) = mm;
        *(float4*)(a + o) = aa;
    }
}

// ---------------------------------------------------------------------------
// fused temporal kernel: [optional regional update of updV -> m (in smem and
// gmem) + x_st accumulation] then V_out[n][u] = sum_t m[n][t] * Lt[t][u]
// with fused 6-dot partials. Block = (chain, 128-row tile). 8x4 thread tile.
// ---------------------------------------------------------------------------
__global__ void __launch_bounds__(256) k_fusedT(
    const float* __restrict__ Lt,
    int updV, int updL, int updS, int rUpd,
    int inIdx, int secIdx, int outIdx,
    int readPP, int writePP)
{
    __shared__ float sX[128][68];     // m tile, [n_local][t]
    __shared__ float sL[32][68];      // Lt k-chunk
    __shared__ float scal[4];
    __shared__ float red[8][6];
    int chain = blockIdx.x, rt = blockIdx.y, tid = threadIdx.x;
    int base = chain * SLAB + rt * 128 * TT;

    if (updV >= 0) {
        if (tid == 0) derive_scalars(readPP, chain, rUpd, scal);
        __syncthreads();
        float d1 = scal[0], d2 = scal[1], inv = scal[2], th = scal[3];
        float* V = g_slab + updV * CSZ + base;
        const float* L = g_slab + updL * CSZ + base;
        const float* S = (updS >= 0) ? (g_slab + updS * CSZ + base) : nullptr;
        float* A = g_slab + ACCS * CSZ + base;
        #pragma unroll
        for (int it = 0; it < 8; it++) {
            int idx = it * 256 + tid;
            int n = idx >> 4, t4 = (idx & 15) << 2;
            int o = n * TT + t4;
            float4 v = *(float4*)(V + o);
            float4 l = *(const float4*)(L + o);
            float4 s4 = S ? *(const float4*)(S + o) : make_float4(0.f, 0.f, 0.f, 0.f);
            float4 m;
            m.x = (v.x - d1 * l.x - d2 * s4.x) * inv;
            m.y = (v.y - d1 * l.y - d2 * s4.y) * inv;
            m.z = (v.z - d1 * l.z - d2 * s4.z) * inv;
            m.w = (v.w - d1 * l.w - d2 * s4.w) * inv;
            *(float4*)(V + o) = m;
            float4 a = *(float4*)(A + o);
            a.x += th * m.x; a.y += th * m.y; a.z += th * m.z; a.w += th * m.w;
            *(float4*)(A + o) = a;
            *(float4*)&sX[n][t4] = m;
        }
    } else {
        const float* X = g_slab + inIdx * CSZ + base;
        #pragma unroll
        for (int it = 0; it < 8; it++) {
            int idx = it * 256 + tid;
            int n = idx >> 4, t4 = (idx & 15) << 2;
            *(float4*)&sX[n][t4] = *(const float4*)(X + n * TT + t4);
        }
    }

    int tx = tid & 15, ty = tid >> 4;
    float acc[8][4] = {};
    for (int kc = 0; kc < 2; kc++) {
        __syncthreads();
        #pragma unroll
        for (int it = 0; it < 2; it++) {
            int li = it * 256 + tid;
            int r = li >> 4, c4 = (li & 15) << 2;
            *(float4*)&sL[r][c4] = *(const float4*)(Lt + (kc * 32 + r) * TT + c4);
        }
        __syncthreads();
        #pragma unroll 4
        for (int k = 0; k < 32; k++) {
            float b[4];
            *(float4*)b = *(float4*)&sL[k][tx * 4];
            float a[8];
            #pragma unroll
            for (int i = 0; i < 8; i++) a[i] = sX[ty * 8 + i][kc * 32 + k];
            #pragma unroll
            for (int i = 0; i < 8; i++)
                #pragma unroll
                for (int j = 0; j < 4; j++) acc[i][j] += a[i] * b[j];
        }
    }

    float* V = g_slab + outIdx * CSZ + base;
    const float* S2 = (secIdx >= 0) ? (g_slab + secIdx * CSZ + base) : nullptr;
    float p1 = 0, p2 = 0, p3 = 0, p4 = 0, p5 = 0, p6 = 0;
    #pragma unroll
    for (int i = 0; i < 8; i++) {
        int n = ty * 8 + i;
        float4 lv = *(float4*)&sX[n][tx * 4];
        float4 sv = S2 ? *(const float4*)(S2 + n * TT + tx * 4)
                       : make_float4(0.f, 0.f, 0.f, 0.f);
        float4 vv = make_float4(acc[i][0], acc[i][1], acc[i][2], acc[i][3]);
        *(float4*)(V + n * TT + tx * 4) = vv;
        p1 += vv.x * lv.x + vv.y * lv.y + vv.z * lv.z + vv.w * lv.w;
        p2 += vv.x * sv.x + vv.y * sv.y + vv.z * sv.z + vv.w * sv.w;
        p3 += vv.x * vv.x + vv.y * vv.y + vv.z * vv.z + vv.w * vv.w;
        p4 += lv.x * sv.x + lv.y * sv.y + lv.z * sv.z + lv.w * sv.w;
        p5 += lv.x * lv.x + lv.y * lv.y + lv.z * lv.z + lv.w * lv.w;
        p6 += sv.x * sv.x + sv.y * sv.y + sv.z * sv.z + sv.w * sv.w;
    }
    float r6[6] = {p1, p2, p3, p4, p5, p6};
    #pragma unroll
    for (int s = 0; s < 6; s++) {
        float w = warp_sum(r6[s]);
        if ((tid & 31) == 0) red[tid >> 5][s] = w;
    }
    __syncthreads();
    if (tid < 6) {
        float t = 0.f;
        #pragma unroll
        for (int w = 0; w < 8; w++) t += red[w][tid];
        g_part[writePP][chain][rt][tid] = t;
    }
}

// ---------------------------------------------------------------------------
// fused spatial kernel: [optional regional update of updV slab (independent
// of the GEMM operands)] then V[n][t] = sum_m Ls[n][m] * X[m][t], K=512 in
// 16 chunks of 32, with fused 6-dot partials. Block = (chain, 128-row tile).
// ---------------------------------------------------------------------------
__global__ void __launch_bounds__(256) k_spatial(
    const float* __restrict__ Ls,
    int updV, int updL, int updS, int rUpd,
    int inIdx, int secIdx, int outIdx,
    int readPP, int writePP)
{
    __shared__ float sA[128][36];     // Ls rows chunk, [n_local][k_local]
    __shared__ float sB[32][68];      // X chunk, [k_local][t]
    __shared__ float scal[4];
    __shared__ float red[8][6];
    int chain = blockIdx.x, nt = blockIdx.y, tid = threadIdx.x;
    int base = chain * SLAB + nt * 128 * TT;

    if (updV >= 0) {
        if (tid == 0) derive_scalars(readPP, chain, rUpd, scal);
        __syncthreads();
        float d1 = scal[0], d2 = scal[1], inv = scal[2], th = scal[3];
        float* V = g_slab + updV * CSZ + base;
        const float* L = g_slab + updL * CSZ + base;
        const float* S = (updS >= 0) ? (g_slab + updS * CSZ + base) : nullptr;
        float* A = g_slab + ACCS * CSZ + base;
        #pragma unroll
        for (int it = 0; it < 8; it++) {
            int idx = it * 256 + tid;
            int n = idx >> 4, t4 = (idx & 15) << 2;
            int o = n * TT + t4;
            float4 v = *(float4*)(V + o);
            float4 l = *(const float4*)(L + o);
            float4 s4 = S ? *(const float4*)(S + o) : make_float4(0.f, 0.f, 0.f, 0.f);
            float4 m;
            m.x = (v.x - d1 * l.x - d2 * s4.x) * inv;
            m.y = (v.y - d1 * l.y - d2 * s4.y) * inv;
            m.z = (v.z - d1 * l.z - d2 * s4.z) * inv;
            m.w = (v.w - d1 * l.w - d2 * s4.w) * inv;
            *(float4*)(V + o) = m;
            float4 a = *(float4*)(A + o);
            a.x += th * m.x; a.y += th * m.y; a.z += th * m.z; a.w += th * m.w;
            *(float4*)(A + o) = a;
        }
    }

    const float* Xc = g_slab + inIdx * CSZ + chain * SLAB;   // full slab (read only)
    int tx = tid & 15, ty = tid >> 4;
    float acc[8][4] = {};
    for (int kc = 0; kc < 16; kc++) {
        __syncthreads();
        #pragma unroll
        for (int it = 0; it < 4; it++) {
            int li = it * 256 + tid;
            int r = li >> 3, c4 = (li & 7) << 2;
            *(float4*)&sA[r][c4] =
                *(const float4*)(Ls + (nt * 128 + r) * NN + kc * 32 + c4);
        }
        #pragma unroll
        for (int it = 0; it < 2; it++) {
            int li = it * 256 + tid;
            int r = li >> 4, c4 = (li & 15) << 2;
            *(float4*)&sB[r][c4] = *(const float4*)(Xc + (kc * 32 + r) * TT + c4);
        }
        __syncthreads();
        #pragma unroll 4
        for (int k = 0; k < 32; k++) {
            float b[4];
            *(float4*)b = *(float4*)&sB[k][tx * 4];
            float a[8];
            #pragma unroll
            for (int i = 0; i < 8; i++) a[i] = sA[ty * 8 + i][k];
            #pragma unroll
            for (int i = 0; i < 8; i++)
                #pragma unroll
                for (int j = 0; j < 4; j++) acc[i][j] += a[i] * b[j];
        }
    }

    const float* Lrows = Xc + nt * 128 * TT;   // last_s values at output rows
    const float* S2 = (secIdx >= 0) ? (g_slab + secIdx * CSZ + base) : nullptr;
    float* V = g_slab + outIdx * CSZ + base;
    float p1 = 0, p2 = 0, p3 = 0, p4 = 0, p5 = 0, p6 = 0;
    #pragma unroll
    for (int i = 0; i < 8; i++) {
        int n = ty * 8 + i;
        float4 lv = *(const float4*)(Lrows + n * TT + tx * 4);
        float4 sv = S2 ? *(const float4*)(S2 + n * TT + tx * 4)
                       : make_float4(0.f, 0.f, 0.f, 0.f);
        float4 vv = make_float4(acc[i][0], acc[i][1], acc[i][2], acc[i][3]);
        *(float4*)(V + n * TT + tx * 4) = vv;
        p1 += vv.x * lv.x + vv.y * lv.y + vv.z * lv.z + vv.w * lv.w;
        p2 += vv.x * sv.x + vv.y * sv.y + vv.z * sv.z + vv.w * sv.w;
        p3 += vv.x * vv.x + vv.y * vv.y + vv.z * vv.z + vv.w * vv.w;
        p4 += lv.x * sv.x + lv.y * sv.y + lv.z * sv.z + lv.w * sv.w;
        p5 += lv.x * lv.x + lv.y * lv.y + lv.z * lv.z + lv.w * lv.w;
        p6 += sv.x * sv.x + sv.y * sv.y + sv.z * sv.z + sv.w * sv.w;
    }
    float r6[6] = {p1, p2, p3, p4, p5, p6};
    #pragma unroll
    for (int s = 0; s < 6; s++) {
        float w = warp_sum(r6[s]);
        if ((tid & 31) == 0) red[tid >> 5][s] = w;
    }
    __syncthreads();
    if (tid < 6) {
        float t = 0.f;
        #pragma unroll
        for (int w = 0; w < 8; w++) t += red[w][tid];
        g_part[writePP][chain][nt][tid] = t;
    }
}

// ---------------------------------------------------------------------------
// standalone update (used once, for r=65): A += theta * m   (m not persisted)
// ---------------------------------------------------------------------------
__global__ void __launch_bounds__(256) k_update(int vIdx, int lIdx, int sIdx,
                                                int rUpd, int readPP) {
    int chain = blockIdx.x, seg = blockIdx.y;
    __shared__ float scal[4];
    int tid = threadIdx.x;
    if (tid == 0) derive_scalars(readPP, chain, rUpd, scal);
    __syncthreads();
    float d1 = scal[0], d2 = scal[1], inv = scal[2], th = scal[3];

    int base = chain * SLAB + seg * 2048;
    const float* V = g_slab + vIdx * CSZ + base;
    const float* L = g_slab + lIdx * CSZ + base;
    const float* S = (sIdx >= 0) ? (g_slab + sIdx * CSZ + base) : nullptr;
    float* A = g_slab + ACCS * CSZ + base;
    #pragma unroll
    for (int it = 0; it < 2; it++) {
        int o = (it * 256 + tid) * 4;
        float4 v = *(const float4*)(V + o);
        float4 l = *(const float4*)(L + o);
        float4 s4 = S ? *(const float4*)(S + o) : make_float4(0.f, 0.f, 0.f, 0.f);
        float4 a = *(float4*)(A + o);
        a.x += th * (v.x - d1 * l.x - d2 * s4.x) * inv;
        a.y += th * (v.y - d1 * l.y - d2 * s4.y) * inv;
        a.z += th * (v.z - d1 * l.z - d2 * s4.z) * inv;
        a.w += th * (v.w - d1 * l.w - d2 * s4.w) * inv;
        *(float4*)(A + o) = a;
    }
}

// ---------------------------------------------------------------------------
// final: out[b,o,n,t] = BN(W_mlp @ cat(x, x_st) + b)   with BN folded into W,b
// ---------------------------------------------------------------------------
__global__ void __launch_bounds__(256) k_final(const float* __restrict__ x,
                                               const float* __restrict__ wm,
                                               const float* __restrict__ bm,
                                               const float* __restrict__ gam,
                                               const float* __restrict__ bet,
                                               const float* __restrict__ mea,
                                               const float* __restrict__ var,
                                               float* __restrict__ out) {
    int b = blockIdx.x;
    int ng = blockIdx.y;                 // group of 4 n values
    __shared__ float sV[4][32][65];
    __shared__ float sW[64][32];
    __shared__ float sb2[64];
    int tid = threadIdx.x;

    for (int i = tid; i < 2048; i += 256) {
        int o = i >> 5, c = i & 31;
        float inv = gam[o] * rsqrtf(var[o] + 1e-5f);
        sW[o][c] = wm[o * 32 + c] * inv;
    }
    if (tid < 64) {
        float inv = gam[tid] * rsqrtf(var[tid] + 1e-5f);
        sb2[tid] = bm[tid] * inv + bet[tid] - mea[tid] * inv;
    }
    for (int i = tid; i < 8192; i += 256) {
        int t = i & 63, c = (i >> 6) & 31, nn = i >> 11;
        int n = ng * 4 + nn;
        float val;
        if (c < 16) val = x[((b * CC + c) * NN + n) * TT + t];
        else        val = g_slab[ACCS * CSZ + (b * CC + (c - 16)) * SLAB + n * TT + t];
        sV[nn][c][t] = val;
    }
    __syncthreads();

    int tg = tid & 63, og = tid >> 6;
    for (int oo = 0; oo < 16; oo++) {
        int o = og * 16 + oo;
        float w[32];
        #pragma unroll
        for (int c = 0; c < 32; c++) w[c] = sW[o][c];
        float bb = sb2[o];
        #pragma unroll
        for (int nn = 0; nn < 4; nn++) {
            float s = bb;
            #pragma unroll
            for (int c = 0; c < 32; c++) s += w[c] * sV[nn][c][tg];
            int n = ng * 4 + nn;
            out[((b * 64 + o) * NN + n) * TT + tg] = s;
        }
    }
}

// ---------------------------------------------------------------------------
// host: 69-node launch sequence (graph-capturable: launches only)
// ---------------------------------------------------------------------------
extern "C" void kernel_launch(void* const* d_in, const int* in_sizes, int n_in,
                              void* d_out, int out_size) {
    const float* x   = (const float*)d_in[0];
    const float* Ls  = (const float*)d_in[1];
    const float* Lt  = (const float*)d_in[2];
    const float* STE = (const float*)d_in[3];
    const float* w1  = (const float*)d_in[4];
    const float* b1  = (const float*)d_in[5];
    const float* w2  = (const float*)d_in[6];
    const float* b2  = (const float*)d_in[7];
    const float* wm  = (const float*)d_in[8];
    const float* bm  = (const float*)d_in[9];
    const float* gam = (const float*)d_in[10];
    const float* bet = (const float*)d_in[11];
    const float* mea = (const float*)d_in[12];
    const float* var = (const float*)d_in[13];
    float* out = (float*)d_out;
    (void)in_sizes; (void)n_in; (void)out_size;

    k_theta<<<1, 288>>>(STE, w1, b1, w2, b2);
    k_init<<<64, 256>>>(x);

    struct Pend { int v, l, s, r, pp; };
    Pend pend{-1, -1, -1, -1, 0};
    int pp = 0;
    int last_s = 0, sec_s = -1, last_t = 0, sec_t = -1;
    int r = 1;
    auto pick = [&]() {
        for (int k = 0; k < 6; k++)
            if (k != last_s && k != sec_s && k != last_t && k != sec_t) return k;
        return -1;
    };
    for (int i = 0; i <= 10; i++) {
        if (i > 0) {
            int f = pick();
            k_spatial<<<dim3(64, 4), 256>>>(Ls, pend.v, pend.l, pend.s, pend.r,
                                            last_s, sec_s, f, pend.pp, pp);
            pend = {f, last_s, sec_s, r, pp}; pp ^= 1;
            sec_s = last_s; last_s = f; last_t = f; sec_t = -1; r++;
        }
        for (int j = 0; j < 5; j++) {
            int f = pick();
            k_fusedT<<<dim3(64, 4), 256>>>(Lt, pend.v, pend.l, pend.s, pend.r,
                                           last_t, sec_t, f, pend.pp, pp);
            pend = {f, last_t, sec_t, r, pp}; pp ^= 1;
            sec_t = last_t; last_t = f; r++;
        }
    }
    k_update<<<dim3(64, 16), 256>>>(pend.v, pend.l, pend.s, pend.r, pend.pp);
    k_final<<<dim3(4, 128), 256>>>(x, wm, bm, gam, bet, mea, var, out);
}

// round 6
// speedup vs baseline: 1.2111x; 1.2111x over previous
#include <cuda_runtime.h>

// ---------------------------------------------------------------------------
// ST_Block: 66-step spatio-temporal orthogonal basis recursion + fused MLP/BN.
//
// Per step r the producing GEMM kernel also emits 6 full-slab dot products
// (deterministic tree reduction into g_part ping-pong). The *next* kernel
// derives the Gram-Schmidt coefficients + analytic residual norm from those
// scalars and performs the normalization + theta-accumulation as a
// region-local prologue (fused update). Only the very last step needs a
// standalone update. 69 graph nodes total, no atomics.
//
// R6 change vs R5: tile sizes cut to restore occupancy (temporal 32-row
// tiles / 1024 blocks, spatial 64-row tiles / 512 blocks). g_part carries a
// variable producer tile count (8 spatial, 16 temporal).
// ---------------------------------------------------------------------------

#define BB   4
#define CC   16
#define CH   64              // B*C chains
#define NN   512
#define TT   64
#define SLAB (NN*TT)         // 32768 floats per chain slab
#define CSZ  (CH*SLAB)       // floats per full slab
#define NSLAB 7
#define ACCS  6              // slab index reserved for x_st accumulator
#define RTOT  66

__device__ __align__(16) float g_slab[NSLAB * CSZ];   // ~58.7 MB scratch
__device__ float g_part[2][CH][16][6];                // ping-pong dot partials
__device__ float g_theta[BB][RTOT];

__device__ __forceinline__ float warp_sum(float v) {
    v += __shfl_down_sync(0xffffffffu, v, 16);
    v += __shfl_down_sync(0xffffffffu, v, 8);
    v += __shfl_down_sync(0xffffffffu, v, 4);
    v += __shfl_down_sync(0xffffffffu, v, 2);
    v += __shfl_down_sync(0xffffffffu, v, 1);
    return v;
}

// Derive d1, d2, 1/norm, theta from the 6 summed dots.
//   d1 = <V,L>;  d2 = <V,S> - d1*<L,S>
//   ||rst2||^2 = p3 - 2 d1 p1 - 2 d2 p2 + d1^2 p5 + d2^2 p6 + 2 d1 d2 p4
__device__ __forceinline__ void derive_scalars(int readPP, int chain, int rUpd,
                                               int nTiles, float* sc) {
    float p[6];
    #pragma unroll
    for (int c = 0; c < 6; c++) {
        float t = 0.f;
        for (int tl = 0; tl < nTiles; tl++) t += g_part[readPP][chain][tl][c];
        p[c] = t;
    }
    float d1 = p[0];
    float d2 = p[1] - d1 * p[3];
    float n2 = p[2] - 2.f * d1 * p[0] - 2.f * d2 * p[1]
             + d1 * d1 * p[4] + d2 * d2 * p[5] + 2.f * d1 * d2 * p[3];
    sc[0] = d1;
    sc[1] = d2;
    sc[2] = 1.f / fmaxf(sqrtf(fmaxf(n2, 0.f)), 1e-8f);
    sc[3] = g_theta[chain >> 4][rUpd];
}

// ---------------------------------------------------------------------------
// theta: tiny MLP on STE. theta[b][q*11+p] = relu(h2[b,p,q])
// ---------------------------------------------------------------------------
__global__ void k_theta(const float* __restrict__ STE, const float* __restrict__ w1,
                        const float* __restrict__ b1, const float* __restrict__ w2,
                        const float* __restrict__ b2) {
    int idx = threadIdx.x;
    if (idx >= BB * RTOT) return;
    int b = idx / RTOT, rr = idx % RTOT;
    int q = rr / 11, p = rr % 11;
    float acc = b2[p];
    #pragma unroll
    for (int s = 0; s < 10; s++) {
        float h1 = b1[q];
        #pragma unroll
        for (int t = 0; t < 5; t++)
            h1 += w1[q * 5 + t] * STE[b * 50 + t * 10 + s];
        acc += w2[p * 10 + s] * h1;
    }
    g_theta[b][rr] = fmaxf(acc, 0.f);
}

// ---------------------------------------------------------------------------
// init: m00 = x / max(||x||_F, eps) into slab 0; acc = theta_0 * m00
// ---------------------------------------------------------------------------
__global__ void __launch_bounds__(256) k_init(const float* __restrict__ x) {
    int chain = blockIdx.x;
    const float* xp = x + chain * SLAB;
    float* m = g_slab + 0 * CSZ + chain * SLAB;
    float* a = g_slab + ACCS * CSZ + chain * SLAB;
    int tid = threadIdx.x;

    float s = 0.f;
    #pragma unroll
    for (int i = 0; i < 32; i++) {
        float4 v = *(const float4*)(xp + (i * 256 + tid) * 4);
        s += v.x * v.x + v.y * v.y + v.z * v.z + v.w * v.w;
    }
    __shared__ float red[8];
    __shared__ float sinv;
    float w = warp_sum(s);
    if ((tid & 31) == 0) red[tid >> 5] = w;
    __syncthreads();
    if (tid == 0) {
        float t = 0.f;
        #pragma unroll
        for (int k = 0; k < 8; k++) t += red[k];
        sinv = 1.f / fmaxf(sqrtf(t), 1e-8f);
    }
    __syncthreads();
    float inv = sinv;
    float th = g_theta[chain >> 4][0];
    #pragma unroll
    for (int i = 0; i < 32; i++) {
        int o = (i * 256 + tid) * 4;
        float4 v = *(const float4*)(xp + o);
        float4 mm, aa;
        mm.x = v.x * inv; mm.y = v.y * inv; mm.z = v.z * inv; mm.w = v.w * inv;
        aa.x = th * mm.x; aa.y = th * mm.y; aa.z = th * mm.z; aa.w = th * mm.w;
        *(float4*)(m + o) = mm;
        *(float4*)(a + o) = aa;
    }
}

// ---------------------------------------------------------------------------
// fused temporal kernel: [optional regional update of updV -> m (into smem
// and gmem) + x_st accumulation] then V_out[n][u] = sum_t m[n][t] * Lt[t][u]
// with fused 6-dot partials. Block = (chain, 32-row tile) -> grid (64,16).
// Thread tile 2x4; smem ~26 KB; target ~85% occupancy.
// ---------------------------------------------------------------------------
__global__ void __launch_bounds__(256) k_fusedT(
    const float* __restrict__ Lt,
    int updV, int updL, int updS, int rUpd, int pendTiles,
    int inIdx, int secIdx, int outIdx,
    int readPP, int writePP)
{
    __shared__ float sL[64][68];      // full Lt
    __shared__ float sX[32][68];      // m tile, [n_local][t]
    __shared__ float scal[4];
    __shared__ float red[8][6];
    int chain = blockIdx.x, rt = blockIdx.y, tid = threadIdx.x;
    int base = chain * SLAB + rt * 32 * TT;

    // Lt load (independent of the prologue; overlaps it)
    #pragma unroll
    for (int it = 0; it < 4; it++) {
        int li = it * 256 + tid;                 // 0..1023
        int r = li >> 4, c4 = (li & 15) << 2;
        *(float4*)&sL[r][c4] = *(const float4*)(Lt + r * TT + c4);
    }

    if (updV >= 0) {
        if (tid == 0) derive_scalars(readPP, chain, rUpd, pendTiles, scal);
        __syncthreads();
        float d1 = scal[0], d2 = scal[1], inv = scal[2], th = scal[3];
        float* V = g_slab + updV * CSZ + base;
        const float* L = g_slab + updL * CSZ + base;
        const float* S = (updS >= 0) ? (g_slab + updS * CSZ + base) : nullptr;
        float* A = g_slab + ACCS * CSZ + base;
        #pragma unroll
        for (int it = 0; it < 2; it++) {
            int idx = it * 256 + tid;            // 0..511
            int n = idx >> 4, t4 = (idx & 15) << 2;
            int o = n * TT + t4;
            float4 v = *(float4*)(V + o);
            float4 l = *(const float4*)(L + o);
            float4 s4 = S ? *(const float4*)(S + o) : make_float4(0.f, 0.f, 0.f, 0.f);
            float4 m;
            m.x = (v.x - d1 * l.x - d2 * s4.x) * inv;
            m.y = (v.y - d1 * l.y - d2 * s4.y) * inv;
            m.z = (v.z - d1 * l.z - d2 * s4.z) * inv;
            m.w = (v.w - d1 * l.w - d2 * s4.w) * inv;
            *(float4*)(V + o) = m;
            float4 a = *(float4*)(A + o);
            a.x += th * m.x; a.y += th * m.y; a.z += th * m.z; a.w += th * m.w;
            *(float4*)(A + o) = a;
            *(float4*)&sX[n][t4] = m;
        }
    } else {
        const float* X = g_slab + inIdx * CSZ + base;
        #pragma unroll
        for (int it = 0; it < 2; it++) {
            int idx = it * 256 + tid;
            int n = idx >> 4, t4 = (idx & 15) << 2;
            *(float4*)&sX[n][t4] = *(const float4*)(X + n * TT + t4);
        }
    }
    __syncthreads();

    int tx = tid & 15, ty = tid >> 4;
    float acc[2][4] = {};
    #pragma unroll 8
    for (int k = 0; k < 64; k++) {
        float b4[4];
        *(float4*)b4 = *(float4*)&sL[k][tx << 2];
        float a0 = sX[ty][k];
        float a1 = sX[ty + 16][k];
        #pragma unroll
        for (int j = 0; j < 4; j++) {
            acc[0][j] += a0 * b4[j];
            acc[1][j] += a1 * b4[j];
        }
    }

    float* V = g_slab + outIdx * CSZ + base;
    const float* S2 = (secIdx >= 0) ? (g_slab + secIdx * CSZ + base) : nullptr;
    float p1 = 0, p2 = 0, p3 = 0, p4 = 0, p5 = 0, p6 = 0;
    #pragma unroll
    for (int i = 0; i < 2; i++) {
        int n = ty + 16 * i;
        float4 lv = *(float4*)&sX[n][tx << 2];
        float4 sv = S2 ? *(const float4*)(S2 + n * TT + (tx << 2))
                       : make_float4(0.f, 0.f, 0.f, 0.f);
        float4 vv = make_float4(acc[i][0], acc[i][1], acc[i][2], acc[i][3]);
        *(float4*)(V + n * TT + (tx << 2)) = vv;
        p1 += vv.x * lv.x + vv.y * lv.y + vv.z * lv.z + vv.w * lv.w;
        p2 += vv.x * sv.x + vv.y * sv.y + vv.z * sv.z + vv.w * sv.w;
        p3 += vv.x * vv.x + vv.y * vv.y + vv.z * vv.z + vv.w * vv.w;
        p4 += lv.x * sv.x + lv.y * sv.y + lv.z * sv.z + lv.w * sv.w;
        p5 += lv.x * lv.x + lv.y * lv.y + lv.z * lv.z + lv.w * lv.w;
        p6 += sv.x * sv.x + sv.y * sv.y + sv.z * sv.z + sv.w * sv.w;
    }
    float r6[6] = {p1, p2, p3, p4, p5, p6};
    #pragma unroll
    for (int s = 0; s < 6; s++) {
        float w = warp_sum(r6[s]);
        if ((tid & 31) == 0) red[tid >> 5][s] = w;
    }
    __syncthreads();
    if (tid < 6) {
        float t = 0.f;
        #pragma unroll
        for (int w = 0; w < 8; w++) t += red[w][tid];
        g_part[writePP][chain][rt][tid] = t;
    }
}

// ---------------------------------------------------------------------------
// fused spatial kernel: [optional regional update of updV slab (independent
// of the GEMM operands)] then V[n][t] = sum_m Ls[n][m] * X[m][t], K=512 in
// 8 chunks of 64, with fused 6-dot partials.
// Block = (chain, 64-row tile) -> grid (64,8). Thread tile 4x4.
// ---------------------------------------------------------------------------
__global__ void __launch_bounds__(256) k_spatial(
    const float* __restrict__ Ls,
    int updV, int updL, int updS, int rUpd, int pendTiles,
    int inIdx, int secIdx, int outIdx,
    int readPP, int writePP)
{
    __shared__ float sA[64][68];      // Ls rows chunk, [n_local][k_local]
    __shared__ float sB[64][68];      // X chunk, [k_local][t]
    __shared__ float scal[4];
    __shared__ float red[8][6];
    int chain = blockIdx.x, nt = blockIdx.y, tid = threadIdx.x;
    int base = chain * SLAB + nt * 64 * TT;

    if (updV >= 0) {
        if (tid == 0) derive_scalars(readPP, chain, rUpd, pendTiles, scal);
        __syncthreads();
        float d1 = scal[0], d2 = scal[1], inv = scal[2], th = scal[3];
        float* V = g_slab + updV * CSZ + base;
        const float* L = g_slab + updL * CSZ + base;
        const float* S = (updS >= 0) ? (g_slab + updS * CSZ + base) : nullptr;
        float* A = g_slab + ACCS * CSZ + base;
        #pragma unroll
        for (int it = 0; it < 4; it++) {
            int idx = it * 256 + tid;            // 0..1023
            int n = idx >> 4, t4 = (idx & 15) << 2;
            int o = n * TT + t4;
            float4 v = *(float4*)(V + o);
            float4 l = *(const float4*)(L + o);
            float4 s4 = S ? *(const float4*)(S + o) : make_float4(0.f, 0.f, 0.f, 0.f);
            float4 m;
            m.x = (v.x - d1 * l.x - d2 * s4.x) * inv;
            m.y = (v.y - d1 * l.y - d2 * s4.y) * inv;
            m.z = (v.z - d1 * l.z - d2 * s4.z) * inv;
            m.w = (v.w - d1 * l.w - d2 * s4.w) * inv;
            *(float4*)(V + o) = m;
            float4 a = *(float4*)(A + o);
            a.x += th * m.x; a.y += th * m.y; a.z += th * m.z; a.w += th * m.w;
            *(float4*)(A + o) = a;
        }
    }

    const float* Xc = g_slab + inIdx * CSZ + chain * SLAB;   // full slab (read only)
    int tx = tid & 15, ty = tid >> 4;
    float acc[4][4] = {};
    for (int kc = 0; kc < 8; kc++) {
        __syncthreads();
        #pragma unroll
        for (int it = 0; it < 4; it++) {
            int li = it * 256 + tid;
            int r = li >> 4, c4 = (li & 15) << 2;
            *(float4*)&sA[r][c4] =
                *(const float4*)(Ls + (nt * 64 + r) * NN + kc * 64 + c4);
            *(float4*)&sB[r][c4] = *(const float4*)(Xc + (kc * 64 + r) * TT + c4);
        }
        __syncthreads();
        #pragma unroll 8
        for (int k = 0; k < 64; k++) {
            float b4[4];
            *(float4*)b4 = *(float4*)&sB[k][tx << 2];
            float a[4];
            #pragma unroll
            for (int i = 0; i < 4; i++) a[i] = sA[ty + 16 * i][k];
            #pragma unroll
            for (int i = 0; i < 4; i++)
                #pragma unroll
                for (int j = 0; j < 4; j++) acc[i][j] += a[i] * b4[j];
        }
    }

    const float* Lrows = Xc + nt * 64 * TT;   // last_s values at output rows
    const float* S2 = (secIdx >= 0) ? (g_slab + secIdx * CSZ + base) : nullptr;
    float* V = g_slab + outIdx * CSZ + base;
    float p1 = 0, p2 = 0, p3 = 0, p4 = 0, p5 = 0, p6 = 0;
    #pragma unroll
    for (int i = 0; i < 4; i++) {
        int n = ty + 16 * i;
        float4 lv = *(const float4*)(Lrows + n * TT + (tx << 2));
        float4 sv = S2 ? *(const float4*)(S2 + n * TT + (tx << 2))
                       : make_float4(0.f, 0.f, 0.f, 0.f);
        float4 vv = make_float4(acc[i][0], acc[i][1], acc[i][2], acc[i][3]);
        *(float4*)(V + n * TT + (tx << 2)) = vv;
        p1 += vv.x * lv.x + vv.y * lv.y + vv.z * lv.z + vv.w * lv.w;
        p2 += vv.x * sv.x + vv.y * sv.y + vv.z * sv.z + vv.w * sv.w;
        p3 += vv.x * vv.x + vv.y * vv.y + vv.z * vv.z + vv.w * vv.w;
        p4 += lv.x * sv.x + lv.y * sv.y + lv.z * sv.z + lv.w * sv.w;
        p5 += lv.x * lv.x + lv.y * lv.y + lv.z * lv.z + lv.w * lv.w;
        p6 += sv.x * sv.x + sv.y * sv.y + sv.z * sv.z + sv.w * sv.w;
    }
    float r6[6] = {p1, p2, p3, p4, p5, p6};
    #pragma unroll
    for (int s = 0; s < 6; s++) {
        float w = warp_sum(r6[s]);
        if ((tid & 31) == 0) red[tid >> 5][s] = w;
    }
    __syncthreads();
    if (tid < 6) {
        float t = 0.f;
        #pragma unroll
        for (int w = 0; w < 8; w++) t += red[w][tid];
        g_part[writePP][chain][nt][tid] = t;
    }
}

// ---------------------------------------------------------------------------
// standalone update (used once, for r=65): A += theta * m   (m not persisted)
// ---------------------------------------------------------------------------
__global__ void __launch_bounds__(256) k_update(int vIdx, int lIdx, int sIdx,
                                                int rUpd, int pendTiles,
                                                int readPP) {
    int chain = blockIdx.x, seg = blockIdx.y;
    __shared__ float scal[4];
    int tid = threadIdx.x;
    if (tid == 0) derive_scalars(readPP, chain, rUpd, pendTiles, scal);
    __syncthreads();
    float d1 = scal[0], d2 = scal[1], inv = scal[2], th = scal[3];

    int base = chain * SLAB + seg * 2048;
    const float* V = g_slab + vIdx * CSZ + base;
    const float* L = g_slab + lIdx * CSZ + base;
    const float* S = (sIdx >= 0) ? (g_slab + sIdx * CSZ + base) : nullptr;
    float* A = g_slab + ACCS * CSZ + base;
    #pragma unroll
    for (int it = 0; it < 2; it++) {
        int o = (it * 256 + tid) * 4;
        float4 v = *(const float4*)(V + o);
        float4 l = *(const float4*)(L + o);
        float4 s4 = S ? *(const float4*)(S + o) : make_float4(0.f, 0.f, 0.f, 0.f);
        float4 a = *(float4*)(A + o);
        a.x += th * (v.x - d1 * l.x - d2 * s4.x) * inv;
        a.y += th * (v.y - d1 * l.y - d2 * s4.y) * inv;
        a.z += th * (v.z - d1 * l.z - d2 * s4.z) * inv;
        a.w += th * (v.w - d1 * l.w - d2 * s4.w) * inv;
        *(float4*)(A + o) = a;
    }
}

// ---------------------------------------------------------------------------
// final: out[b,o,n,t] = BN(W_mlp @ cat(x, x_st) + b)   with BN folded into W,b
// ---------------------------------------------------------------------------
__global__ void __launch_bounds__(256) k_final(const float* __restrict__ x,
                                               const float* __restrict__ wm,
                                               const float* __restrict__ bm,
                                               const float* __restrict__ gam,
                                               const float* __restrict__ bet,
                                               const float* __restrict__ mea,
                                               const float* __restrict__ var,
                                               float* __restrict__ out) {
    int b = blockIdx.x;
    int ng = blockIdx.y;                 // group of 4 n values
    __shared__ float sV[4][32][65];
    __shared__ float sW[64][32];
    __shared__ float sb2[64];
    int tid = threadIdx.x;

    for (int i = tid; i < 2048; i += 256) {
        int o = i >> 5, c = i & 31;
        float inv = gam[o] * rsqrtf(var[o] + 1e-5f);
        sW[o][c] = wm[o * 32 + c] * inv;
    }
    if (tid < 64) {
        float inv = gam[tid] * rsqrtf(var[tid] + 1e-5f);
        sb2[tid] = bm[tid] * inv + bet[tid] - mea[tid] * inv;
    }
    for (int i = tid; i < 8192; i += 256) {
        int t = i & 63, c = (i >> 6) & 31, nn = i >> 11;
        int n = ng * 4 + nn;
        float val;
        if (c < 16) val = x[((b * CC + c) * NN + n) * TT + t];
        else        val = g_slab[ACCS * CSZ + (b * CC + (c - 16)) * SLAB + n * TT + t];
        sV[nn][c][t] = val;
    }
    __syncthreads();

    int tg = tid & 63, og = tid >> 6;
    for (int oo = 0; oo < 16; oo++) {
        int o = og * 16 + oo;
        float w[32];
        #pragma unroll
        for (int c = 0; c < 32; c++) w[c] = sW[o][c];
        float bb = sb2[o];
        #pragma unroll
        for (int nn = 0; nn < 4; nn++) {
            float s = bb;
            #pragma unroll
            for (int c = 0; c < 32; c++) s += w[c] * sV[nn][c][tg];
            int n = ng * 4 + nn;
            out[((b * 64 + o) * NN + n) * TT + tg] = s;
        }
    }
}

// ---------------------------------------------------------------------------
// host: 69-node launch sequence (graph-capturable: launches only)
// ---------------------------------------------------------------------------
extern "C" void kernel_launch(void* const* d_in, const int* in_sizes, int n_in,
                              void* d_out, int out_size) {
    const float* x   = (const float*)d_in[0];
    const float* Ls  = (const float*)d_in[1];
    const float* Lt  = (const float*)d_in[2];
    const float* STE = (const float*)d_in[3];
    const float* w1  = (const float*)d_in[4];
    const float* b1  = (const float*)d_in[5];
    const float* w2  = (const float*)d_in[6];
    const float* b2  = (const float*)d_in[7];
    const float* wm  = (const float*)d_in[8];
    const float* bm  = (const float*)d_in[9];
    const float* gam = (const float*)d_in[10];
    const float* bet = (const float*)d_in[11];
    const float* mea = (const float*)d_in[12];
    const float* var = (const float*)d_in[13];
    float* out = (float*)d_out;
    (void)in_sizes; (void)n_in; (void)out_size;

    k_theta<<<1, 288>>>(STE, w1, b1, w2, b2);
    k_init<<<64, 256>>>(x);

    struct Pend { int v, l, s, r, pp, tiles; };
    Pend pend{-1, -1, -1, -1, 0, 0};
    int pp = 0;
    int last_s = 0, sec_s = -1, last_t = 0, sec_t = -1;
    int r = 1;
    auto pick = [&]() {
        for (int k = 0; k < 6; k++)
            if (k != last_s && k != sec_s && k != last_t && k != sec_t) return k;
        return -1;
    };
    for (int i = 0; i <= 10; i++) {
        if (i > 0) {
            int f = pick();
            k_spatial<<<dim3(64, 8), 256>>>(Ls, pend.v, pend.l, pend.s, pend.r,
                                            pend.tiles, last_s, sec_s, f,
                                            pend.pp, pp);
            pend = {f, last_s, sec_s, r, pp, 8}; pp ^= 1;
            sec_s = last_s; last_s = f; last_t = f; sec_t = -1; r++;
        }
        for (int j = 0; j < 5; j++) {
            int f = pick();
            k_fusedT<<<dim3(64, 16), 256>>>(Lt, pend.v, pend.l, pend.s, pend.r,
                                            pend.tiles, last_t, sec_t, f,
                                            pend.pp, pp);
            pend = {f, last_t, sec_t, r, pp, 16}; pp ^= 1;
            sec_t = last_t; last_t = f; r++;
        }
    }
    k_update<<<dim3(64, 16), 256>>>(pend.v, pend.l, pend.s, pend.r, pend.tiles,
                                    pend.pp);
    k_final<<<dim3(4, 128), 256>>>(x, wm, bm, gam, bet, mea, var, out);
}